// round 1
// baseline (speedup 1.0000x reference)
#include <cuda_runtime.h>
#include <math.h>

#define LEN 2048
#define DIM 2048
#define NH 16
#define HD 128
#define SCALE 0.08838834764831845f  /* 1/sqrt(128) */

// ---------------- scratch (allocation-free: __device__ globals) ----------------
__device__ float g_qkv[(size_t)LEN * 3 * DIM];        // [L, 3*DIM]
__device__ float g_q[(size_t)NH * LEN * HD];          // [H, L, D]
__device__ float g_k[(size_t)NH * LEN * HD];          // [H, L, D]
__device__ float g_vt[(size_t)NH * HD * LEN];         // [H, D, L]  (V transposed)
__device__ float g_s[(size_t)NH * LEN * LEN];         // [H, L, L]  logits/probs
__device__ float g_o[(size_t)LEN * DIM];              // [L, H*D]

// ---------------- generic fp32 NT GEMM: C[m,n] = alpha * sum_k A[m,k]*B[n,k] (+bias[n]) ----
// Tile 128x128, BK=16, 256 threads, 8x8 per-thread microtile.
// Requires: M,N multiples of 128; K multiple of 16; lda/ldb/ldc multiples of 4.
__global__ __launch_bounds__(256, 2)
void gemm_nt(const float* __restrict__ A, const float* __restrict__ B,
             float* __restrict__ C,
             int M, int N, int K, int lda, int ldb, int ldc,
             long long sA, long long sB, long long sC,
             float alpha, const float* __restrict__ bias)
{
    const int bz = blockIdx.z;
    A += (long long)bz * sA;
    B += (long long)bz * sB;
    C += (long long)bz * sC;

    __shared__ float As[16][132];
    __shared__ float Bs[16][132];

    const int tid = threadIdx.x;
    const int tx = tid & 15;          // 0..15 -> n
    const int ty = tid >> 4;          // 0..15 -> m
    const int m0 = blockIdx.y * 128;
    const int n0 = blockIdx.x * 128;

    const int lk4 = tid & 3;          // which float4 along k
    const int lrow = tid >> 2;        // 0..63

    float acc[8][8];
#pragma unroll
    for (int i = 0; i < 8; ++i)
#pragma unroll
        for (int j = 0; j < 8; ++j) acc[i][j] = 0.0f;

    for (int k0 = 0; k0 < K; k0 += 16) {
#pragma unroll
        for (int p = 0; p < 2; ++p) {
            const int r = lrow + p * 64;
            float4 va = *reinterpret_cast<const float4*>(
                &A[(long long)(m0 + r) * lda + k0 + lk4 * 4]);
            As[lk4 * 4 + 0][r] = va.x;
            As[lk4 * 4 + 1][r] = va.y;
            As[lk4 * 4 + 2][r] = va.z;
            As[lk4 * 4 + 3][r] = va.w;
            float4 vb = *reinterpret_cast<const float4*>(
                &B[(long long)(n0 + r) * ldb + k0 + lk4 * 4]);
            Bs[lk4 * 4 + 0][r] = vb.x;
            Bs[lk4 * 4 + 1][r] = vb.y;
            Bs[lk4 * 4 + 2][r] = vb.z;
            Bs[lk4 * 4 + 3][r] = vb.w;
        }
        __syncthreads();

#pragma unroll
        for (int k = 0; k < 16; ++k) {
            float a[8], b[8];
            *reinterpret_cast<float4*>(a)     = *reinterpret_cast<const float4*>(&As[k][ty * 8]);
            *reinterpret_cast<float4*>(a + 4) = *reinterpret_cast<const float4*>(&As[k][ty * 8 + 4]);
            *reinterpret_cast<float4*>(b)     = *reinterpret_cast<const float4*>(&Bs[k][tx * 8]);
            *reinterpret_cast<float4*>(b + 4) = *reinterpret_cast<const float4*>(&Bs[k][tx * 8 + 4]);
#pragma unroll
            for (int i = 0; i < 8; ++i)
#pragma unroll
                for (int j = 0; j < 8; ++j)
                    acc[i][j] = fmaf(a[i], b[j], acc[i][j]);
        }
        __syncthreads();
    }

#pragma unroll
    for (int i = 0; i < 8; ++i) {
        const int m = m0 + ty * 8 + i;
#pragma unroll
        for (int j = 0; j < 8; j += 4) {
            const int n = n0 + tx * 8 + j;
            float4 v;
            v.x = acc[i][j + 0] * alpha;
            v.y = acc[i][j + 1] * alpha;
            v.z = acc[i][j + 2] * alpha;
            v.w = acc[i][j + 3] * alpha;
            if (bias) {
                v.x += bias[n + 0];
                v.y += bias[n + 1];
                v.z += bias[n + 2];
                v.w += bias[n + 3];
            }
            *reinterpret_cast<float4*>(&C[(long long)m * ldc + n]) = v;
        }
    }
}

// ---------------- QK RMSNorm + RoPE + V transpose ----------------
// grid (L, H), 128 threads (one per head-dim element)
__global__ void qknorm_rope(const float* __restrict__ pe,
                            const float* __restrict__ qs,
                            const float* __restrict__ ks)
{
    const int l = blockIdx.x;
    const int h = blockIdx.y;
    const int d = threadIdx.x;

    const float* base = g_qkv + (size_t)l * (3 * DIM) + h * HD;
    float q = base[d];
    float k = base[DIM + d];
    float v = base[2 * DIM + d];

    float sq = q * q, sk = k * k;
#pragma unroll
    for (int o = 16; o; o >>= 1) {
        sq += __shfl_xor_sync(0xffffffffu, sq, o);
        sk += __shfl_xor_sync(0xffffffffu, sk, o);
    }
    __shared__ float rq[4], rk[4];
    const int w = d >> 5;
    if ((d & 31) == 0) { rq[w] = sq; rk[w] = sk; }
    __syncthreads();
    sq = rq[0] + rq[1] + rq[2] + rq[3];
    sk = rk[0] + rk[1] + rk[2] + rk[3];

    const float rrq = rsqrtf(sq * (1.0f / HD) + 1e-6f);
    const float rrk = rsqrtf(sk * (1.0f / HD) + 1e-6f);
    float qn = q * rrq * qs[d];
    float kn = k * rrk * ks[d];

    // RoPE: rotation with partner element within the (2j, 2j+1) pair
    const float qp = __shfl_xor_sync(0xffffffffu, qn, 1);
    const float kp = __shfl_xor_sync(0xffffffffu, kn, 1);
    const int j = d >> 1, a = d & 1;
    const float* p = pe + (size_t)l * (HD / 2) * 4 + j * 4 + a * 2;
    const float q0 = a ? qp : qn, q1 = a ? qn : qp;
    const float k0 = a ? kp : kn, k1 = a ? kn : kp;
    const float qr = p[0] * q0 + p[1] * q1;
    const float kr = p[0] * k0 + p[1] * k1;

    const size_t idx = ((size_t)h * LEN + l) * HD + d;
    g_q[idx] = qr;
    g_k[idx] = kr;
    g_vt[((size_t)h * HD + d) * LEN + l] = v;
}

// ---------------- row softmax over g_s, in place ----------------
// grid = H*L blocks, 256 threads; row length = LEN = 2048 (8 per thread)
__global__ void softmax_rows()
{
    float* s = g_s + (size_t)blockIdx.x * LEN;
    const int t = threadIdx.x;

    float vals[8];
    float mx = -INFINITY;
#pragma unroll
    for (int i = 0; i < 8; ++i) {
        vals[i] = s[t + i * 256];
        mx = fmaxf(mx, vals[i]);
    }
#pragma unroll
    for (int o = 16; o; o >>= 1)
        mx = fmaxf(mx, __shfl_xor_sync(0xffffffffu, mx, o));
    __shared__ float red[8];
    const int w = t >> 5;
    if ((t & 31) == 0) red[w] = mx;
    __syncthreads();
    mx = red[0];
#pragma unroll
    for (int i = 1; i < 8; ++i) mx = fmaxf(mx, red[i]);

    float sum = 0.0f;
#pragma unroll
    for (int i = 0; i < 8; ++i) {
        vals[i] = __expf(vals[i] - mx);
        sum += vals[i];
    }
#pragma unroll
    for (int o = 16; o; o >>= 1)
        sum += __shfl_xor_sync(0xffffffffu, sum, o);
    __syncthreads();
    if ((t & 31) == 0) red[w] = sum;
    __syncthreads();
    sum = red[0];
#pragma unroll
    for (int i = 1; i < 8; ++i) sum += red[i];

    const float inv = 1.0f / sum;
#pragma unroll
    for (int i = 0; i < 8; ++i)
        s[t + i * 256] = vals[i] * inv;
}

// ---------------- launch ----------------
extern "C" void kernel_launch(void* const* d_in, const int* in_sizes, int n_in,
                              void* d_out, int out_size)
{
    const float* x      = (const float*)d_in[0];  // [L, DIM]
    const float* pe     = (const float*)d_in[1];  // [L, D/2, 2, 2]
    const float* w_qkv  = (const float*)d_in[2];  // [3*DIM, DIM]
    const float* q_sc   = (const float*)d_in[3];  // [D]
    const float* k_sc   = (const float*)d_in[4];  // [D]
    const float* w_proj = (const float*)d_in[5];  // [DIM, DIM]
    const float* b_proj = (const float*)d_in[6];  // [DIM]
    float* out = (float*)d_out;

    float *p_qkv, *p_q, *p_k, *p_vt, *p_s, *p_o;
    cudaGetSymbolAddress((void**)&p_qkv, g_qkv);
    cudaGetSymbolAddress((void**)&p_q,   g_q);
    cudaGetSymbolAddress((void**)&p_k,   g_k);
    cudaGetSymbolAddress((void**)&p_vt,  g_vt);
    cudaGetSymbolAddress((void**)&p_s,   g_s);
    cudaGetSymbolAddress((void**)&p_o,   g_o);

    // 1) QKV = x @ w_qkv^T : [2048, 6144]
    gemm_nt<<<dim3(6144 / 128, 2048 / 128, 1), 256>>>(
        x, w_qkv, p_qkv, 2048, 6144, 2048, 2048, 2048, 6144,
        0, 0, 0, 1.0f, nullptr);

    // 2) QK RMSNorm + RoPE + V transpose
    qknorm_rope<<<dim3(LEN, NH), HD>>>(pe, q_sc, k_sc);

    // 3) S = scale * Q K^T per head : [H, 2048, 2048]
    gemm_nt<<<dim3(2048 / 128, 2048 / 128, NH), 256>>>(
        p_q, p_k, p_s, 2048, 2048, HD, HD, HD, 2048,
        (long long)LEN * HD, (long long)LEN * HD, (long long)LEN * LEN,
        SCALE, nullptr);

    // 4) row softmax
    softmax_rows<<<NH * LEN, 256>>>();

    // 5) O = P @ V per head : write into g_o[L, H*D] at column offset h*128
    gemm_nt<<<dim3(HD / 128, 2048 / 128, NH), 256>>>(
        p_s, p_vt, p_o, 2048, HD, 2048, 2048, 2048, 2048,
        (long long)LEN * LEN, (long long)HD * LEN, (long long)HD,
        1.0f, nullptr);

    // 6) out = O @ w_proj^T + b_proj : [2048, 2048]
    gemm_nt<<<dim3(2048 / 128, 2048 / 128, 1), 256>>>(
        p_o, w_proj, out, 2048, 2048, 2048, 2048, 2048, 2048,
        0, 0, 0, 1.0f, b_proj);
}

// round 2
// speedup vs baseline: 1.7434x; 1.7434x over previous
#include <cuda_runtime.h>
#include <cuda_bf16.h>
#include <math.h>

#define LEN 2048
#define DIM 2048
#define NH 16
#define HD 128
#define SCALE 0.08838834764831845f  /* 1/sqrt(128) */

// ---------------- scratch (allocation-free: __device__ globals) ----------------
__device__ float g_qkv[(size_t)LEN * 3 * DIM];        // [L, 3*DIM]
__device__ float g_q[(size_t)NH * LEN * HD];          // [H, L, D]
__device__ float g_k[(size_t)NH * LEN * HD];          // [H, L, D]
__device__ float g_vt[(size_t)NH * HD * LEN];         // [H, D, L]  (V transposed)
__device__ float g_s[(size_t)NH * LEN * LEN];         // [H, L, L]  logits/probs
__device__ float g_o[(size_t)LEN * DIM];              // [L, H*D]

// ---------------- helpers ----------------
static __device__ __forceinline__ unsigned cvta_smem(const void* p) {
    return (unsigned)__cvta_generic_to_shared(p);
}

// split two fp32 into packed bf16x2 hi and lo parts (x ~= hi + lo)
static __device__ __forceinline__ void split2(float x0, float x1,
                                              unsigned& hi, unsigned& lo) {
    unsigned h;
    asm("cvt.rn.bf16x2.f32 %0, %1, %2;" : "=r"(h) : "f"(x1), "f"(x0));
    float h0 = __uint_as_float(h << 16);
    float h1 = __uint_as_float(h & 0xffff0000u);
    float l0 = x0 - h0;
    float l1 = x1 - h1;
    unsigned l;
    asm("cvt.rn.bf16x2.f32 %0, %1, %2;" : "=r"(l) : "f"(l1), "f"(l0));
    hi = h; lo = l;
}

#define LDSM4(r0, r1, r2, r3, addr)                                         \
    asm volatile("ldmatrix.sync.aligned.m8n8.x4.shared.b16 {%0,%1,%2,%3}, [%4];" \
                 : "=r"(r0), "=r"(r1), "=r"(r2), "=r"(r3) : "r"(addr))

#define MMA16816(d, a, b0_, b1_)                                            \
    asm volatile("mma.sync.aligned.m16n8k16.row.col.f32.bf16.bf16.f32 "    \
                 "{%0,%1,%2,%3},{%4,%5,%6,%7},{%8,%9},{%0,%1,%2,%3};"      \
                 : "+f"(d[0]), "+f"(d[1]), "+f"(d[2]), "+f"(d[3])           \
                 : "r"(a[0]), "r"(a[1]), "r"(a[2]), "r"(a[3]),              \
                   "r"(b0_), "r"(b1_))

// ---------------- bf16x3 tensor-core NT GEMM ----------------
// C[m,n] = alpha * sum_k A[m,k]*B[n,k] (+ bias[n])
// Block tile 128x128, BK=32, 256 threads (8 warps, warp tile 64x32).
// M,N multiples of 128; K multiple of 32; lda/ldb multiples of 4.
__global__ __launch_bounds__(256, 1)
void gemm_nt_tc(const float* __restrict__ A, const float* __restrict__ B,
                float* __restrict__ C,
                int M, int N, int K, int lda, int ldb, int ldc,
                long long sA, long long sB, long long sC,
                float alpha, const float* __restrict__ bias)
{
    const int bz = blockIdx.z;
    A += (long long)bz * sA;
    B += (long long)bz * sB;
    C += (long long)bz * sC;

    // u32 = 2 bf16; row pitch 20 u32 = 40 bf16 = 80 bytes (LDSM conflict-free)
    __shared__ unsigned sAh[128 * 20];
    __shared__ unsigned sAl[128 * 20];
    __shared__ unsigned sBh[128 * 20];
    __shared__ unsigned sBl[128 * 20];

    const int tid  = threadIdx.x;
    const int wid  = tid >> 5;
    const int lane = tid & 31;
    const int wm = (wid >> 2) * 64;   // warp row offset (0 or 64)
    const int wn = (wid & 3) * 32;    // warp col offset (0..96)
    const int m0 = blockIdx.y * 128;
    const int n0 = blockIdx.x * 128;

    float acc[4][4][4];
#pragma unroll
    for (int i = 0; i < 4; ++i)
#pragma unroll
        for (int j = 0; j < 4; ++j)
#pragma unroll
            for (int v = 0; v < 4; ++v) acc[i][j][v] = 0.0f;

    const unsigned baseAh = cvta_smem(sAh);
    const unsigned baseAl = cvta_smem(sAl);
    const unsigned baseBh = cvta_smem(sBh);
    const unsigned baseBl = cvta_smem(sBl);

    // fragment byte offsets within a tile buffer
    unsigned offA[4], offB[2];
#pragma unroll
    for (int mt = 0; mt < 4; ++mt) {
        int r = wm + mt * 16 + (lane & 15);
        int cb = ((lane >> 4) & 1) * 16;       // k-offset 8 bf16 = 16B
        offA[mt] = r * 80 + cb;
    }
#pragma unroll
    for (int p = 0; p < 2; ++p) {
        int r = wn + p * 16 + (lane & 7) + ((lane >> 4) & 1) * 8;
        int cb = ((lane >> 3) & 1) * 16;
        offB[p] = r * 80 + cb;
    }

    for (int k0 = 0; k0 < K; k0 += 32) {
        // ---- load 128x32 fp32 tiles of A and B, split to bf16 hi/lo ----
#pragma unroll
        for (int i = 0; i < 4; ++i) {
            int idx = tid + i * 256;       // 0..1023
            int row = idx >> 3;            // 0..127
            int kk  = idx & 7;             // float4 index along k
            int s   = row * 20 + kk * 2;

            float4 va = *reinterpret_cast<const float4*>(
                &A[(long long)(m0 + row) * lda + k0 + kk * 4]);
            unsigned h0, l0, h1, l1;
            split2(va.x, va.y, h0, l0);
            split2(va.z, va.w, h1, l1);
            sAh[s] = h0; sAh[s + 1] = h1;
            sAl[s] = l0; sAl[s + 1] = l1;

            float4 vb = *reinterpret_cast<const float4*>(
                &B[(long long)(n0 + row) * ldb + k0 + kk * 4]);
            split2(vb.x, vb.y, h0, l0);
            split2(vb.z, vb.w, h1, l1);
            sBh[s] = h0; sBh[s + 1] = h1;
            sBl[s] = l0; sBl[s + 1] = l1;
        }
        __syncthreads();

        // ---- two k16 steps ----
#pragma unroll
        for (int ks = 0; ks < 2; ++ks) {
            const unsigned kb = ks * 32;   // 16 bf16 = 32 bytes
            unsigned ah[4][4], al[4][4], bh[2][4], bl[2][4];
#pragma unroll
            for (int mt = 0; mt < 4; ++mt) {
                LDSM4(ah[mt][0], ah[mt][1], ah[mt][2], ah[mt][3], baseAh + offA[mt] + kb);
                LDSM4(al[mt][0], al[mt][1], al[mt][2], al[mt][3], baseAl + offA[mt] + kb);
            }
#pragma unroll
            for (int p = 0; p < 2; ++p) {
                LDSM4(bh[p][0], bh[p][1], bh[p][2], bh[p][3], baseBh + offB[p] + kb);
                LDSM4(bl[p][0], bl[p][1], bl[p][2], bl[p][3], baseBl + offB[p] + kb);
            }
#pragma unroll
            for (int mt = 0; mt < 4; ++mt) {
#pragma unroll
                for (int nt = 0; nt < 4; ++nt) {
                    const int p = nt >> 1, q = (nt & 1) * 2;
                    MMA16816(acc[mt][nt], ah[mt], bh[p][q], bh[p][q + 1]);
                    MMA16816(acc[mt][nt], ah[mt], bl[p][q], bl[p][q + 1]);
                    MMA16816(acc[mt][nt], al[mt], bh[p][q], bh[p][q + 1]);
                }
            }
        }
        __syncthreads();
    }

    // ---- epilogue ----
    const int g  = lane >> 2;
    const int tg = lane & 3;
#pragma unroll
    for (int mt = 0; mt < 4; ++mt) {
#pragma unroll
        for (int nt = 0; nt < 4; ++nt) {
            const int r = m0 + wm + mt * 16 + g;
            const int c = n0 + wn + nt * 8 + tg * 2;
            float bx = 0.0f, by = 0.0f;
            if (bias) { bx = bias[c]; by = bias[c + 1]; }
            float2 v0, v1;
            v0.x = acc[mt][nt][0] * alpha + bx;
            v0.y = acc[mt][nt][1] * alpha + by;
            v1.x = acc[mt][nt][2] * alpha + bx;
            v1.y = acc[mt][nt][3] * alpha + by;
            *reinterpret_cast<float2*>(&C[(long long)r * ldc + c]) = v0;
            *reinterpret_cast<float2*>(&C[(long long)(r + 8) * ldc + c]) = v1;
        }
    }
}

// ---------------- QK RMSNorm + RoPE + V transpose ----------------
__global__ void qknorm_rope(const float* __restrict__ pe,
                            const float* __restrict__ qs,
                            const float* __restrict__ ks)
{
    const int l = blockIdx.x;
    const int h = blockIdx.y;
    const int d = threadIdx.x;

    const float* base = g_qkv + (size_t)l * (3 * DIM) + h * HD;
    float q = base[d];
    float k = base[DIM + d];
    float v = base[2 * DIM + d];

    float sq = q * q, sk = k * k;
#pragma unroll
    for (int o = 16; o; o >>= 1) {
        sq += __shfl_xor_sync(0xffffffffu, sq, o);
        sk += __shfl_xor_sync(0xffffffffu, sk, o);
    }
    __shared__ float rq[4], rk[4];
    const int w = d >> 5;
    if ((d & 31) == 0) { rq[w] = sq; rk[w] = sk; }
    __syncthreads();
    sq = rq[0] + rq[1] + rq[2] + rq[3];
    sk = rk[0] + rk[1] + rk[2] + rk[3];

    const float rrq = rsqrtf(sq * (1.0f / HD) + 1e-6f);
    const float rrk = rsqrtf(sk * (1.0f / HD) + 1e-6f);
    float qn = q * rrq * qs[d];
    float kn = k * rrk * ks[d];

    const float qp = __shfl_xor_sync(0xffffffffu, qn, 1);
    const float kp = __shfl_xor_sync(0xffffffffu, kn, 1);
    const int j = d >> 1, a = d & 1;
    const float* p = pe + (size_t)l * (HD / 2) * 4 + j * 4 + a * 2;
    const float q0 = a ? qp : qn, q1 = a ? qn : qp;
    const float k0 = a ? kp : kn, k1 = a ? kn : kp;
    const float qr = p[0] * q0 + p[1] * q1;
    const float kr = p[0] * k0 + p[1] * k1;

    const size_t idx = ((size_t)h * LEN + l) * HD + d;
    g_q[idx] = qr;
    g_k[idx] = kr;
    g_vt[((size_t)h * HD + d) * LEN + l] = v;
}

// ---------------- row softmax over g_s, in place ----------------
__global__ void softmax_rows()
{
    float* s = g_s + (size_t)blockIdx.x * LEN;
    const int t = threadIdx.x;

    float vals[8];
    float mx = -INFINITY;
#pragma unroll
    for (int i = 0; i < 8; ++i) {
        vals[i] = s[t + i * 256];
        mx = fmaxf(mx, vals[i]);
    }
#pragma unroll
    for (int o = 16; o; o >>= 1)
        mx = fmaxf(mx, __shfl_xor_sync(0xffffffffu, mx, o));
    __shared__ float red[8];
    const int w = t >> 5;
    if ((t & 31) == 0) red[w] = mx;
    __syncthreads();
    mx = red[0];
#pragma unroll
    for (int i = 1; i < 8; ++i) mx = fmaxf(mx, red[i]);

    float sum = 0.0f;
#pragma unroll
    for (int i = 0; i < 8; ++i) {
        vals[i] = __expf(vals[i] - mx);
        sum += vals[i];
    }
#pragma unroll
    for (int o = 16; o; o >>= 1)
        sum += __shfl_xor_sync(0xffffffffu, sum, o);
    __syncthreads();
    if ((t & 31) == 0) red[w] = sum;
    __syncthreads();
    sum = red[0];
#pragma unroll
    for (int i = 1; i < 8; ++i) sum += red[i];

    const float inv = 1.0f / sum;
#pragma unroll
    for (int i = 0; i < 8; ++i)
        s[t + i * 256] = vals[i] * inv;
}

// ---------------- launch ----------------
extern "C" void kernel_launch(void* const* d_in, const int* in_sizes, int n_in,
                              void* d_out, int out_size)
{
    const float* x      = (const float*)d_in[0];  // [L, DIM]
    const float* pe     = (const float*)d_in[1];  // [L, D/2, 2, 2]
    const float* w_qkv  = (const float*)d_in[2];  // [3*DIM, DIM]
    const float* q_sc   = (const float*)d_in[3];  // [D]
    const float* k_sc   = (const float*)d_in[4];  // [D]
    const float* w_proj = (const float*)d_in[5];  // [DIM, DIM]
    const float* b_proj = (const float*)d_in[6];  // [DIM]
    float* out = (float*)d_out;

    float *p_qkv, *p_q, *p_k, *p_vt, *p_s, *p_o;
    cudaGetSymbolAddress((void**)&p_qkv, g_qkv);
    cudaGetSymbolAddress((void**)&p_q,   g_q);
    cudaGetSymbolAddress((void**)&p_k,   g_k);
    cudaGetSymbolAddress((void**)&p_vt,  g_vt);
    cudaGetSymbolAddress((void**)&p_s,   g_s);
    cudaGetSymbolAddress((void**)&p_o,   g_o);

    // 1) QKV = x @ w_qkv^T : [2048, 6144]
    gemm_nt_tc<<<dim3(6144 / 128, 2048 / 128, 1), 256>>>(
        x, w_qkv, p_qkv, 2048, 6144, 2048, 2048, 2048, 6144,
        0, 0, 0, 1.0f, nullptr);

    // 2) QK RMSNorm + RoPE + V transpose
    qknorm_rope<<<dim3(LEN, NH), HD>>>(pe, q_sc, k_sc);

    // 3) S = scale * Q K^T per head : [H, 2048, 2048]
    gemm_nt_tc<<<dim3(2048 / 128, 2048 / 128, NH), 256>>>(
        p_q, p_k, p_s, 2048, 2048, HD, HD, HD, 2048,
        (long long)LEN * HD, (long long)LEN * HD, (long long)LEN * LEN,
        SCALE, nullptr);

    // 4) row softmax
    softmax_rows<<<NH * LEN, 256>>>();

    // 5) O = P @ V per head : write into g_o[L, H*D] at column offset h*128
    gemm_nt_tc<<<dim3(HD / 128, 2048 / 128, NH), 256>>>(
        p_s, p_vt, p_o, 2048, HD, 2048, 2048, 2048, 2048,
        (long long)LEN * LEN, (long long)HD * LEN, (long long)HD,
        1.0f, nullptr);

    // 6) out = O @ w_proj^T + b_proj : [2048, 2048]
    gemm_nt_tc<<<dim3(2048 / 128, 2048 / 128, 1), 256>>>(
        p_o, w_proj, out, 2048, 2048, 2048, 2048, 2048, 2048,
        0, 0, 0, 1.0f, b_proj);
}

// round 4
// speedup vs baseline: 2.5814x; 1.4807x over previous
#include <cuda_runtime.h>
#include <cuda_bf16.h>
#include <math.h>
#include <stdint.h>

#define LEN 2048
#define DIM 2048
#define NH 16
#define HD 128
#define SCALE 0.08838834764831845f  /* 1/sqrt(128) */

// ---------------- scratch (allocation-free: __device__ globals) ----------------
__device__ float g_qkv[(size_t)LEN * 3 * DIM];               // [L, 3*DIM] fp32
__device__ float g_s[(size_t)NH * LEN * LEN];                // [H, L, L] logits fp32

__device__ __nv_bfloat16 g_xh[(size_t)LEN * DIM];            // x hi/lo
__device__ __nv_bfloat16 g_xl[(size_t)LEN * DIM];
__device__ __nv_bfloat16 g_wqh[(size_t)3 * DIM * DIM];       // w_qkv hi/lo
__device__ __nv_bfloat16 g_wql[(size_t)3 * DIM * DIM];
__device__ __nv_bfloat16 g_wph[(size_t)DIM * DIM];           // w_proj hi/lo
__device__ __nv_bfloat16 g_wpl[(size_t)DIM * DIM];
__device__ __nv_bfloat16 g_qh[(size_t)NH * LEN * HD];        // q hi/lo [H,L,D]
__device__ __nv_bfloat16 g_ql[(size_t)NH * LEN * HD];
__device__ __nv_bfloat16 g_kh[(size_t)NH * LEN * HD];        // k hi/lo [H,L,D]
__device__ __nv_bfloat16 g_kl[(size_t)NH * LEN * HD];
__device__ __nv_bfloat16 g_vth[(size_t)NH * HD * LEN];       // v^T hi/lo [H,D,L]
__device__ __nv_bfloat16 g_vtl[(size_t)NH * HD * LEN];
__device__ __nv_bfloat16 g_ph[(size_t)NH * LEN * LEN];       // probs hi/lo [H,L,L]
__device__ __nv_bfloat16 g_pl[(size_t)NH * LEN * LEN];
__device__ __nv_bfloat16 g_oh[(size_t)LEN * DIM];            // O hi/lo [L, H*D]
__device__ __nv_bfloat16 g_ol[(size_t)LEN * DIM];

// ---------------- helpers ----------------
static __device__ __forceinline__ unsigned cvta_smem(const void* p) {
    return (unsigned)__cvta_generic_to_shared(p);
}

// pack two fp32 into bf16x2 (round-to-nearest)
static __device__ __forceinline__ unsigned pack2(float x0, float x1) {
    unsigned r;
    asm("cvt.rn.bf16x2.f32 %0, %1, %2;" : "=r"(r) : "f"(x1), "f"(x0));
    return r;
}
// split two fp32 into bf16x2 hi and lo
static __device__ __forceinline__ void split2(float x0, float x1,
                                              unsigned& hi, unsigned& lo) {
    unsigned h = pack2(x0, x1);
    float h0 = __uint_as_float(h << 16);
    float h1 = __uint_as_float(h & 0xffff0000u);
    lo = pack2(x0 - h0, x1 - h1);
    hi = h;
}

#define LDSM4(r0, r1, r2, r3, addr)                                         \
    asm volatile("ldmatrix.sync.aligned.m8n8.x4.shared.b16 {%0,%1,%2,%3}, [%4];" \
                 : "=r"(r0), "=r"(r1), "=r"(r2), "=r"(r3) : "r"(addr))

#define MMA16816(d, a, b0_, b1_)                                            \
    asm volatile("mma.sync.aligned.m16n8k16.row.col.f32.bf16.bf16.f32 "    \
                 "{%0,%1,%2,%3},{%4,%5,%6,%7},{%8,%9},{%0,%1,%2,%3};"      \
                 : "+f"(d[0]), "+f"(d[1]), "+f"(d[2]), "+f"(d[3])           \
                 : "r"(a[0]), "r"(a[1]), "r"(a[2]), "r"(a[3]),              \
                   "r"(b0_), "r"(b1_))

#define CP_ASYNC16(dst, src) \
    asm volatile("cp.async.cg.shared.global [%0], [%1], 16;" \
                 :: "r"(dst), "l"(src) : "memory")
#define CP_COMMIT() asm volatile("cp.async.commit_group;" ::: "memory")
#define CP_WAIT1()  asm volatile("cp.async.wait_group 1;" ::: "memory")
#define CP_WAIT0()  asm volatile("cp.async.wait_group 0;" ::: "memory")

// ---------------- bf16x3 tensor-core NT GEMM (pre-split operands) --------------
// C = alpha * (Ah+Al) @ (Bh+Bl)^T (+bias), dropping Al*Bl.
// A: [M,K] bf16 hi/lo, B: [N,K] bf16 hi/lo, both K-contig.
// CTA tile 128x128, BK=64, 256 threads (8 warps, warp tile 64x32),
// double-buffered cp.async pipeline, SW128 swizzle, ldmatrix + mma.sync.
// Requires M,N mult of 128; K mult of 64; lda,ldb mult of 8.
// smem: 2 stages x (Ah,Al,Bh,Bl each 128x64x2B = 16KB) = 128KB
#define GSMEM (2 * 65536)

// loads one 128x64 bf16 tile into swizzled smem (1024 x 16B chunks)
static __device__ __forceinline__ void load_tile(
    unsigned sbase, const __nv_bfloat16* __restrict__ A,
    int ld, int kbase, int tid)
{
#pragma unroll
    for (int i = 0; i < 4; ++i) {
        const int idx = tid + i * 256;
        const int row = idx >> 3;
        const int ch  = idx & 7;
        const unsigned dst = sbase + row * 128 + ((ch * 16) ^ ((row & 7) * 16));
        const __nv_bfloat16* src = A + (long long)row * ld + kbase + ch * 8;
        CP_ASYNC16(dst, src);
    }
}

__global__ __launch_bounds__(256, 1)
void gemm_nt_bf3(const __nv_bfloat16* __restrict__ Ah,
                 const __nv_bfloat16* __restrict__ Al,
                 const __nv_bfloat16* __restrict__ Bh,
                 const __nv_bfloat16* __restrict__ Bl,
                 float* __restrict__ Cf,
                 __nv_bfloat16* __restrict__ Ch,
                 __nv_bfloat16* __restrict__ Cl,
                 int K, int lda, int ldb, int ldc,
                 long long sA, long long sB, long long sC,
                 float alpha, const float* __restrict__ bias)
{
    extern __shared__ char smem[];
    const unsigned smem_b = cvta_smem(smem);

    const int tid  = threadIdx.x;
    const int wid  = tid >> 5;
    const int lane = tid & 31;
    const int wm = (wid >> 2) * 64;
    const int wn = (wid & 3) * 32;
    const int m0 = blockIdx.y * 128;
    const int n0 = blockIdx.x * 128;

    const long long zoff = blockIdx.z;
    Ah += zoff * sA; Al += zoff * sA;
    Bh += zoff * sB; Bl += zoff * sB;
    if (Cf) Cf += zoff * sC;
    if (Ch) { Ch += zoff * sC; Cl += zoff * sC; }

    const __nv_bfloat16* pAh = Ah + (long long)m0 * lda;
    const __nv_bfloat16* pAl = Al + (long long)m0 * lda;
    const __nv_bfloat16* pBh = Bh + (long long)n0 * ldb;
    const __nv_bfloat16* pBl = Bl + (long long)n0 * ldb;

    // fragment address components (swizzle: chunk bits4-6 ^= (row&7)<<4)
    unsigned offA0[4], mskA[4];
    const unsigned cbA = ((lane >> 4) & 1) * 16;
#pragma unroll
    for (int mt = 0; mt < 4; ++mt) {
        const int r = wm + mt * 16 + (lane & 15);
        offA0[mt] = r * 128;
        mskA[mt]  = (r & 7) * 16;
    }
    unsigned offB0[2], mskB[2];
    const unsigned cbB = ((lane >> 3) & 1) * 16;
#pragma unroll
    for (int p = 0; p < 2; ++p) {
        const int r = wn + p * 16 + (lane & 7) + ((lane >> 4) & 1) * 8;
        offB0[p] = r * 128;
        mskB[p]  = (r & 7) * 16;
    }

    float acc[4][4][4];
#pragma unroll
    for (int i = 0; i < 4; ++i)
#pragma unroll
        for (int j = 0; j < 4; ++j)
#pragma unroll
            for (int v = 0; v < 4; ++v) acc[i][j][v] = 0.0f;

    const int nch = K >> 6;

    // prologue: stage 0
    {
        const unsigned sb = smem_b;
        load_tile(sb,          pAh, lda, 0, tid);
        load_tile(sb + 16384,  pAl, lda, 0, tid);
        load_tile(sb + 32768,  pBh, ldb, 0, tid);
        load_tile(sb + 49152,  pBl, ldb, 0, tid);
        CP_COMMIT();
    }

    for (int c = 0; c < nch; ++c) {
        if (c + 1 < nch) {
            const unsigned sb = smem_b + ((c + 1) & 1) * 65536;
            const int kb = (c + 1) * 64;
            load_tile(sb,          pAh, lda, kb, tid);
            load_tile(sb + 16384,  pAl, lda, kb, tid);
            load_tile(sb + 32768,  pBh, ldb, kb, tid);
            load_tile(sb + 49152,  pBl, ldb, kb, tid);
            CP_COMMIT();
            CP_WAIT1();
        } else {
            CP_WAIT0();
        }
        __syncthreads();

        const unsigned sb = smem_b + (c & 1) * 65536;
#pragma unroll
        for (int ks = 0; ks < 4; ++ks) {
            const unsigned kb = ks * 32;
            unsigned ah[4][4], al[4][4], bh[2][4], bl[2][4];
#pragma unroll
            for (int mt = 0; mt < 4; ++mt) {
                const unsigned a0 = sb + offA0[mt] + ((cbA + kb) ^ mskA[mt]);
                LDSM4(ah[mt][0], ah[mt][1], ah[mt][2], ah[mt][3], a0);
                LDSM4(al[mt][0], al[mt][1], al[mt][2], al[mt][3], a0 + 16384);
            }
#pragma unroll
            for (int p = 0; p < 2; ++p) {
                const unsigned b0 = sb + 32768 + offB0[p] + ((cbB + kb) ^ mskB[p]);
                LDSM4(bh[p][0], bh[p][1], bh[p][2], bh[p][3], b0);
                LDSM4(bl[p][0], bl[p][1], bl[p][2], bl[p][3], b0 + 16384);
            }
#pragma unroll
            for (int mt = 0; mt < 4; ++mt) {
#pragma unroll
                for (int nt = 0; nt < 4; ++nt) {
                    const int p = nt >> 1, q = (nt & 1) * 2;
                    MMA16816(acc[mt][nt], ah[mt], bh[p][q], bh[p][q + 1]);
                    MMA16816(acc[mt][nt], ah[mt], bl[p][q], bl[p][q + 1]);
                    MMA16816(acc[mt][nt], al[mt], bh[p][q], bh[p][q + 1]);
                }
            }
        }
        __syncthreads();
    }

    // epilogue
    const int g  = lane >> 2;
    const int tg = lane & 3;
#pragma unroll
    for (int mt = 0; mt < 4; ++mt) {
#pragma unroll
        for (int nt = 0; nt < 4; ++nt) {
            const int r = m0 + wm + mt * 16 + g;
            const int c = n0 + wn + nt * 8 + tg * 2;
            float bx = 0.0f, by = 0.0f;
            if (bias) { bx = bias[c]; by = bias[c + 1]; }
            float v00 = acc[mt][nt][0] * alpha + bx;
            float v01 = acc[mt][nt][1] * alpha + by;
            float v10 = acc[mt][nt][2] * alpha + bx;
            float v11 = acc[mt][nt][3] * alpha + by;
            if (Cf) {
                *reinterpret_cast<float2*>(&Cf[(long long)r * ldc + c]) =
                    make_float2(v00, v01);
                *reinterpret_cast<float2*>(&Cf[(long long)(r + 8) * ldc + c]) =
                    make_float2(v10, v11);
            }
            if (Ch) {
                unsigned h0, l0, h1, l1;
                split2(v00, v01, h0, l0);
                split2(v10, v11, h1, l1);
                *reinterpret_cast<unsigned*>(&Ch[(long long)r * ldc + c]) = h0;
                *reinterpret_cast<unsigned*>(&Cl[(long long)r * ldc + c]) = l0;
                *reinterpret_cast<unsigned*>(&Ch[(long long)(r + 8) * ldc + c]) = h1;
                *reinterpret_cast<unsigned*>(&Cl[(long long)(r + 8) * ldc + c]) = l1;
            }
        }
    }
}

// ---------------- pre-split x, w_qkv, w_proj into bf16 hi/lo ----------------
// one thread = one float4; segments: x (1M f4), w_qkv (3M f4), w_proj (1M f4)
#define SEG_X  (LEN * DIM / 4)
#define SEG_WQ (3 * DIM * DIM / 4)
#define SEG_WP (DIM * DIM / 4)
__global__ void split_inputs(const float* __restrict__ x,
                             const float* __restrict__ wq,
                             const float* __restrict__ wp)
{
    const int i = blockIdx.x * blockDim.x + threadIdx.x;
    const float* src;
    __nv_bfloat16 *dh, *dl;
    int j;
    if (i < SEG_X)                  { src = x;  dh = g_xh;  dl = g_xl;  j = i; }
    else if (i < SEG_X + SEG_WQ)    { src = wq; dh = g_wqh; dl = g_wql; j = i - SEG_X; }
    else if (i < SEG_X + SEG_WQ + SEG_WP)
                                    { src = wp; dh = g_wph; dl = g_wpl; j = i - SEG_X - SEG_WQ; }
    else return;

    float4 v = reinterpret_cast<const float4*>(src)[j];
    unsigned h0, l0, h1, l1;
    split2(v.x, v.y, h0, l0);
    split2(v.z, v.w, h1, l1);
    reinterpret_cast<uint2*>(dh)[j] = make_uint2(h0, h1);
    reinterpret_cast<uint2*>(dl)[j] = make_uint2(l0, l1);
}

// ---------------- QK RMSNorm + RoPE + V transpose (split outputs) ----------------
__global__ void qknorm_rope(const float* __restrict__ pe,
                            const float* __restrict__ qs,
                            const float* __restrict__ ks)
{
    const int l = blockIdx.x;
    const int h = blockIdx.y;
    const int d = threadIdx.x;

    const float* base = g_qkv + (size_t)l * (3 * DIM) + h * HD;
    float q = base[d];
    float k = base[DIM + d];
    float v = base[2 * DIM + d];

    float sq = q * q, sk = k * k;
#pragma unroll
    for (int o = 16; o; o >>= 1) {
        sq += __shfl_xor_sync(0xffffffffu, sq, o);
        sk += __shfl_xor_sync(0xffffffffu, sk, o);
    }
    __shared__ float rq[4], rk[4];
    const int w = d >> 5;
    if ((d & 31) == 0) { rq[w] = sq; rk[w] = sk; }
    __syncthreads();
    sq = rq[0] + rq[1] + rq[2] + rq[3];
    sk = rk[0] + rk[1] + rk[2] + rk[3];

    const float rrq = rsqrtf(sq * (1.0f / HD) + 1e-6f);
    const float rrk = rsqrtf(sk * (1.0f / HD) + 1e-6f);
    float qn = q * rrq * qs[d];
    float kn = k * rrk * ks[d];

    const float qp = __shfl_xor_sync(0xffffffffu, qn, 1);
    const float kp = __shfl_xor_sync(0xffffffffu, kn, 1);
    const int j = d >> 1, a = d & 1;
    const float* p = pe + (size_t)l * (HD / 2) * 4 + j * 4 + a * 2;
    const float q0 = a ? qp : qn, q1 = a ? qn : qp;
    const float k0 = a ? kp : kn, k1 = a ? kn : kp;
    const float qr = p[0] * q0 + p[1] * q1;
    const float kr = p[0] * k0 + p[1] * k1;

    const size_t idx = ((size_t)h * LEN + l) * HD + d;
    __nv_bfloat16 qh = __float2bfloat16_rn(qr);
    __nv_bfloat16 kh = __float2bfloat16_rn(kr);
    g_qh[idx] = qh;
    g_ql[idx] = __float2bfloat16_rn(qr - __bfloat162float(qh));
    g_kh[idx] = kh;
    g_kl[idx] = __float2bfloat16_rn(kr - __bfloat162float(kh));

    const size_t vidx = ((size_t)h * HD + d) * LEN + l;
    __nv_bfloat16 vh = __float2bfloat16_rn(v);
    g_vth[vidx] = vh;
    g_vtl[vidx] = __float2bfloat16_rn(v - __bfloat162float(vh));
}

// ---------------- row softmax: fp32 logits -> bf16 hi/lo probs ----------------
// grid = H*L, 256 threads, each thread owns 8 contiguous elems
__global__ void softmax_rows()
{
    const size_t base = (size_t)blockIdx.x * LEN;
    const float* s = g_s + base;
    const int t = threadIdx.x;
    const int i0 = t * 8;

    float vals[8];
    *reinterpret_cast<float4*>(vals)     = *reinterpret_cast<const float4*>(&s[i0]);
    *reinterpret_cast<float4*>(vals + 4) = *reinterpret_cast<const float4*>(&s[i0 + 4]);

    float mx = -INFINITY;
#pragma unroll
    for (int i = 0; i < 8; ++i) mx = fmaxf(mx, vals[i]);
#pragma unroll
    for (int o = 16; o; o >>= 1)
        mx = fmaxf(mx, __shfl_xor_sync(0xffffffffu, mx, o));
    __shared__ float red[8];
    const int w = t >> 5;
    if ((t & 31) == 0) red[w] = mx;
    __syncthreads();
    mx = red[0];
#pragma unroll
    for (int i = 1; i < 8; ++i) mx = fmaxf(mx, red[i]);

    float sum = 0.0f;
#pragma unroll
    for (int i = 0; i < 8; ++i) {
        vals[i] = __expf(vals[i] - mx);
        sum += vals[i];
    }
#pragma unroll
    for (int o = 16; o; o >>= 1)
        sum += __shfl_xor_sync(0xffffffffu, sum, o);
    __syncthreads();
    if ((t & 31) == 0) red[w] = sum;
    __syncthreads();
    sum = red[0];
#pragma unroll
    for (int i = 1; i < 8; ++i) sum += red[i];

    const float inv = 1.0f / sum;
    unsigned hp[4], lp[4];
#pragma unroll
    for (int i = 0; i < 4; ++i) {
        float p0 = vals[2 * i] * inv;
        float p1 = vals[2 * i + 1] * inv;
        split2(p0, p1, hp[i], lp[i]);
    }
    *reinterpret_cast<uint4*>(
        reinterpret_cast<unsigned*>(g_ph) + (base + i0) / 2) =
        make_uint4(hp[0], hp[1], hp[2], hp[3]);
    *reinterpret_cast<uint4*>(
        reinterpret_cast<unsigned*>(g_pl) + (base + i0) / 2) =
        make_uint4(lp[0], lp[1], lp[2], lp[3]);
}

// ---------------- launch ----------------
extern "C" void kernel_launch(void* const* d_in, const int* in_sizes, int n_in,
                              void* d_out, int out_size)
{
    const float* x      = (const float*)d_in[0];  // [L, DIM]
    const float* pe     = (const float*)d_in[1];  // [L, D/2, 2, 2]
    const float* w_qkv  = (const float*)d_in[2];  // [3*DIM, DIM]
    const float* q_sc   = (const float*)d_in[3];  // [D]
    const float* k_sc   = (const float*)d_in[4];  // [D]
    const float* w_proj = (const float*)d_in[5];  // [DIM, DIM]
    const float* b_proj = (const float*)d_in[6];  // [DIM]
    float* out = (float*)d_out;

    float *p_qkv, *p_s;
    __nv_bfloat16 *p_xh, *p_xl, *p_wqh, *p_wql, *p_wph, *p_wpl;
    __nv_bfloat16 *p_qh, *p_ql, *p_kh, *p_kl, *p_vth, *p_vtl;
    __nv_bfloat16 *p_ph, *p_pl, *p_oh, *p_ol;
    cudaGetSymbolAddress((void**)&p_qkv, g_qkv);
    cudaGetSymbolAddress((void**)&p_s,   g_s);
    cudaGetSymbolAddress((void**)&p_xh,  g_xh);
    cudaGetSymbolAddress((void**)&p_xl,  g_xl);
    cudaGetSymbolAddress((void**)&p_wqh, g_wqh);
    cudaGetSymbolAddress((void**)&p_wql, g_wql);
    cudaGetSymbolAddress((void**)&p_wph, g_wph);
    cudaGetSymbolAddress((void**)&p_wpl, g_wpl);
    cudaGetSymbolAddress((void**)&p_qh,  g_qh);
    cudaGetSymbolAddress((void**)&p_ql,  g_ql);
    cudaGetSymbolAddress((void**)&p_kh,  g_kh);
    cudaGetSymbolAddress((void**)&p_kl,  g_kl);
    cudaGetSymbolAddress((void**)&p_vth, g_vth);
    cudaGetSymbolAddress((void**)&p_vtl, g_vtl);
    cudaGetSymbolAddress((void**)&p_ph,  g_ph);
    cudaGetSymbolAddress((void**)&p_pl,  g_pl);
    cudaGetSymbolAddress((void**)&p_oh,  g_oh);
    cudaGetSymbolAddress((void**)&p_ol,  g_ol);

    cudaFuncSetAttribute(gemm_nt_bf3,
                         cudaFuncAttributeMaxDynamicSharedMemorySize, GSMEM);

    // 0) pre-split x, w_qkv, w_proj
    {
        const int total = SEG_X + SEG_WQ + SEG_WP;
        split_inputs<<<(total + 255) / 256, 256>>>(x, w_qkv, w_proj);
    }

    // 1) QKV = x @ w_qkv^T : [2048, 6144] fp32
    gemm_nt_bf3<<<dim3(6144 / 128, 2048 / 128, 1), 256, GSMEM>>>(
        p_xh, p_xl, p_wqh, p_wql, p_qkv, nullptr, nullptr,
        2048, 2048, 2048, 6144, 0, 0, 0, 1.0f, nullptr);

    // 2) QK RMSNorm + RoPE + V transpose (bf16 hi/lo outputs)
    qknorm_rope<<<dim3(LEN, NH), HD>>>(pe, q_sc, k_sc);

    // 3) S = scale * Q K^T per head : [H, 2048, 2048] fp32
    gemm_nt_bf3<<<dim3(2048 / 128, 2048 / 128, NH), 256, GSMEM>>>(
        p_qh, p_ql, p_kh, p_kl, p_s, nullptr, nullptr,
        HD, HD, HD, 2048,
        (long long)LEN * HD, (long long)LEN * HD, (long long)LEN * LEN,
        SCALE, nullptr);

    // 4) row softmax -> bf16 hi/lo probs
    softmax_rows<<<NH * LEN, 256>>>();

    // 5) O = P @ V per head -> bf16 hi/lo into [L, H*D] at column h*128
    gemm_nt_bf3<<<dim3(HD / 128, 2048 / 128, NH), 256, GSMEM>>>(
        p_ph, p_pl, p_vth, p_vtl, nullptr, p_oh, p_ol,
        2048, 2048, 2048, 2048,
        (long long)LEN * LEN, (long long)HD * LEN, (long long)HD,
        1.0f, nullptr);

    // 6) out = O @ w_proj^T + b_proj : [2048, 2048] fp32
    gemm_nt_bf3<<<dim3(2048 / 128, 2048 / 128, 1), 256, GSMEM>>>(
        p_oh, p_ol, p_wph, p_wpl, out, nullptr, nullptr,
        2048, 2048, 2048, 2048, 0, 0, 0, 1.0f, b_proj);
}